// round 2
// baseline (speedup 1.0000x reference)
#include <cuda_runtime.h>
#include <math.h>

// Problem constants
#define BATCH   2048
#define LAT     256
#define HID     1024
#define OUTD    512
#define TSTEPS  100
#define NSUB    10
#define NCTA    128
#define BKK     16
#define LDSA    132   // 128 + 4 pad

enum { MODE_ELU = 0, MODE_EULER = 1, MODE_PLAIN = 2 };

// ---------------------------------------------------------------------------
// Device scratch (no cudaMalloc allowed)
// ---------------------------------------------------------------------------
__device__ float g_zs[(size_t)TSTEPS * BATCH * LAT];
__device__ float g_h1[(size_t)BATCH * HID];
__device__ float g_h2[(size_t)BATCH * HID];
__device__ float g_za[(size_t)BATCH * LAT];
__device__ float g_zb[(size_t)BATCH * LAT];
__device__ float g_Md[(size_t)OUTD * LAT];
__device__ float g_cd[OUTD];

// grid barrier state (self-restoring: even #barriers per launch, count resets)
__device__ unsigned g_cnt;    // zero-init, returns to 0 every launch
__device__ unsigned g_sense;  // zero-init, returns to 0 every launch (even count)

// ---------------------------------------------------------------------------
// Packed f32x2 helpers (2x fp32 FMA throughput; only reachable via PTX)
// ---------------------------------------------------------------------------
__device__ __forceinline__ unsigned long long pack2(float x, float y) {
    unsigned long long r;
    asm("mov.b64 %0, {%1, %2};" : "=l"(r) : "f"(x), "f"(y));
    return r;
}
__device__ __forceinline__ void fma2(unsigned long long& d,
                                     unsigned long long a,
                                     unsigned long long b) {
    asm("fma.rn.f32x2 %0, %1, %2, %0;" : "+l"(d) : "l"(a), "l"(b));
}
__device__ __forceinline__ float2 unpack2(unsigned long long v) {
    float2 f;
    asm("mov.b64 {%0, %1}, %2;" : "=f"(f.x), "=f"(f.y) : "l"(v));
    return f;
}

// ---------------------------------------------------------------------------
// Sense-reversing software grid barrier. Requires all NCTA CTAs co-resident
// (grid=128, 1 CTA/SM on 148+ SMs). Total barriers per launch must be EVEN
// so g_sense ends each launch at 0 (replay-deterministic).
// ---------------------------------------------------------------------------
__device__ __forceinline__ void grid_sync(unsigned* s_sense) {
    __syncthreads();
    if (threadIdx.x == 0) {
        unsigned my = *s_sense ^ 1u;
        *s_sense = my;
        __threadfence();                       // publish this CTA's writes (gpu scope)
        if (atomicAdd(&g_cnt, 1u) == NCTA - 1u) {
            *(volatile unsigned*)&g_cnt = 0u;  // safe: all arrived, none can re-add yet
            __threadfence();
            *(volatile unsigned*)&g_sense = my;
        } else {
            while (*(volatile unsigned*)&g_sense != my) { }
        }
    }
    __syncthreads();
}

// ---------------------------------------------------------------------------
// Fused NT GEMM tile:  C[m,n] = epilogue( sum_k A[m,k]*W[n,k] + bias[n] )
// A loads use __ldcg (L2) — A is produced by other CTAs between barriers.
// ---------------------------------------------------------------------------
template <int BM, int BN, int TM, int TN, int MODE>
__device__ __forceinline__ void gemm_dev(
    const float* __restrict__ A, const float* __restrict__ W,
    const float* __restrict__ bias, const float* __restrict__ Zp,
    float* __restrict__ C, int N, int K, float h, int mBase, int nBase,
    float (&As)[2][BKK][LDSA], float (&Bs)[2][BKK][LDSA]) {

    const int tid = threadIdx.x;
    constexpr int K4  = BKK / 4;
    constexpr int APT = BM * BKK / 4 / 256;
    constexpr int BPT = BN * BKK / 4 / 256;
    const int nT = K / BKK;

    float4 aR[APT], bR[BPT];
    const int ty = tid / (BN / TN);
    const int tx = tid % (BN / TN);
    const int m0 = ty * TM;
    const int n0 = tx * TN;

    unsigned long long acc[TM][TN / 2] = {};

    auto ldgf = [&](int t) {
#pragma unroll
        for (int i = 0; i < APT; i++) {
            int idx = tid + i * 256;
            int row = idx / K4, c4 = idx % K4;
            aR[i] = __ldcg((const float4*)&A[(size_t)(mBase + row) * K + (size_t)t * BKK + c4 * 4]);
        }
#pragma unroll
        for (int i = 0; i < BPT; i++) {
            int idx = tid + i * 256;
            int row = idx / K4, c4 = idx % K4;
            bR[i] = __ldg((const float4*)&W[(size_t)(nBase + row) * K + (size_t)t * BKK + c4 * 4]);
        }
    };
    auto stsf = [&](int buf) {
#pragma unroll
        for (int i = 0; i < APT; i++) {
            int idx = tid + i * 256;
            int row = idx / K4, c4 = idx % K4;
            As[buf][c4 * 4 + 0][row] = aR[i].x;
            As[buf][c4 * 4 + 1][row] = aR[i].y;
            As[buf][c4 * 4 + 2][row] = aR[i].z;
            As[buf][c4 * 4 + 3][row] = aR[i].w;
        }
#pragma unroll
        for (int i = 0; i < BPT; i++) {
            int idx = tid + i * 256;
            int row = idx / K4, c4 = idx % K4;
            Bs[buf][c4 * 4 + 0][row] = bR[i].x;
            Bs[buf][c4 * 4 + 1][row] = bR[i].y;
            Bs[buf][c4 * 4 + 2][row] = bR[i].z;
            Bs[buf][c4 * 4 + 3][row] = bR[i].w;
        }
    };

    ldgf(0);
    stsf(0);
    __syncthreads();

    for (int t = 0; t < nT; ++t) {
        const int cur = t & 1;
        const int nxt = cur ^ 1;
        if (t + 1 < nT) ldgf(t + 1);

#pragma unroll
        for (int k = 0; k < BKK; k++) {
            float a[TM];
#pragma unroll
            for (int i = 0; i < TM; i += 4) {
                float4 v = *(const float4*)&As[cur][k][m0 + i];
                a[i] = v.x; a[i + 1] = v.y; a[i + 2] = v.z; a[i + 3] = v.w;
            }
            unsigned long long bp[TN / 2];
#pragma unroll
            for (int j = 0; j < TN; j += 4) {
                float4 v = *(const float4*)&Bs[cur][k][n0 + j];
                bp[j / 2]     = pack2(v.x, v.y);
                bp[j / 2 + 1] = pack2(v.z, v.w);
            }
#pragma unroll
            for (int i = 0; i < TM; i++) {
                unsigned long long av = pack2(a[i], a[i]);
#pragma unroll
                for (int j = 0; j < TN / 2; j++) fma2(acc[i][j], av, bp[j]);
            }
        }

        if (t + 1 < nT) {
            stsf(nxt);
            __syncthreads();
        }
    }

    // epilogue
#pragma unroll
    for (int i = 0; i < TM; i++) {
        const size_t m = (size_t)(mBase + m0 + i);
#pragma unroll
        for (int j = 0; j < TN; j += 2) {
            const int n = nBase + n0 + j;
            float2 v = unpack2(acc[i][j / 2]);
            float x0 = v.x + __ldg(&bias[n]);
            float x1 = v.y + __ldg(&bias[n + 1]);
            if (MODE == MODE_ELU) {
                x0 = x0 > 0.0f ? x0 : expm1f(x0);
                x1 = x1 > 0.0f ? x1 : expm1f(x1);
            } else if (MODE == MODE_EULER) {
                x0 = __ldcg(&Zp[m * N + n])     + h * x0;
                x1 = __ldcg(&Zp[m * N + n + 1]) + h * x1;
            }
            C[m * N + n]     = x0;
            C[m * N + n + 1] = x1;
        }
    }
}

// ---------------------------------------------------------------------------
// Persistent ODE integrator: 99 intervals x 10 substeps x 3 GEMM phases.
// grid must be exactly <<<NCTA, 256>>>. Barrier count: 1 + 2970 + 1 = 2972 (even).
// ---------------------------------------------------------------------------
__global__ void __launch_bounds__(256, 1)
ode_persistent(const float* __restrict__ z0, const float* __restrict__ tv,
               const float* __restrict__ w1, const float* __restrict__ b1,
               const float* __restrict__ w2, const float* __restrict__ b2,
               const float* __restrict__ w3, const float* __restrict__ b3,
               float* __restrict__ zs, float* __restrict__ h1,
               float* __restrict__ h2, float* __restrict__ za,
               float* __restrict__ zb) {
    __shared__ __align__(16) float As[2][BKK][LDSA];
    __shared__ __align__(16) float Bs[2][BKK][LDSA];
    __shared__ unsigned s_sense;
    if (threadIdx.x == 0) s_sense = 0u;

    // zs[0] = z0
    const int total4 = BATCH * LAT / 4;
    for (int i = blockIdx.x * 256 + threadIdx.x; i < total4; i += NCTA * 256)
        ((float4*)zs)[i] = __ldcg(&((const float4*)z0)[i]);
    grid_sync(&s_sense);                                       // barrier 1

    const size_t BL = (size_t)BATCH * LAT;

    for (int it = 0; it < TSTEPS - 1; ++it) {
        const float hstep = (__ldg(&tv[it + 1]) - __ldg(&tv[it])) * (1.0f / NSUB);
        for (int s = 0; s < NSUB; s++) {
            const float* zin  = (s == 0)        ? zs + (size_t)it * BL
                                                : ((s & 1) ? za : zb);
            float*       zout = (s == NSUB - 1) ? zs + (size_t)(it + 1) * BL
                                                : ((s & 1) ? zb : za);
            {   // h1 = elu(z @ w1.T + b1)   [2048x1024, K=256] 16x8 tiles
                const int mB = (blockIdx.x / 8) * 128, nB = (blockIdx.x % 8) * 128;
                gemm_dev<128, 128, 8, 8, MODE_ELU>(zin, w1, b1, nullptr, h1,
                                                   HID, LAT, 0.f, mB, nB, As, Bs);
            }
            grid_sync(&s_sense);
            {   // h2 = elu(h1 @ w2.T + b2)  [2048x1024, K=1024] 16x8 tiles
                const int mB = (blockIdx.x / 8) * 128, nB = (blockIdx.x % 8) * 128;
                gemm_dev<128, 128, 8, 8, MODE_ELU>(h1, w2, b2, nullptr, h2,
                                                   HID, HID, 0.f, mB, nB, As, Bs);
            }
            grid_sync(&s_sense);
            {   // zout = zin + h*(h2 @ w3.T + b3)  [2048x256, K=1024] 32x4 tiles
                const int mB = (blockIdx.x / 4) * 64, nB = (blockIdx.x % 4) * 64;
                gemm_dev<64, 64, 4, 4, MODE_EULER>(h2, w3, b3, zin, zout,
                                                   LAT, HID, hstep, mB, nB, As, Bs);
            }
            grid_sync(&s_sense);
        }
    }
    grid_sync(&s_sense);   // pad to even barrier count (2972)
}

// ---------------------------------------------------------------------------
// Folded decoder: out = zs @ (h2o_w @ l2h_w).T + (h2o_w @ l2h_b + h2o_b)
// ---------------------------------------------------------------------------
__global__ void __launch_bounds__(256, 1)
decoder_gemm(const float* __restrict__ zs, const float* __restrict__ Md,
             const float* __restrict__ cd, float* __restrict__ out) {
    __shared__ __align__(16) float As[2][BKK][LDSA];
    __shared__ __align__(16) float Bs[2][BKK][LDSA];
    gemm_dev<128, 128, 8, 8, MODE_PLAIN>(zs, Md, cd, nullptr, out,
                                         OUTD, LAT, 0.f,
                                         blockIdx.y * 128, blockIdx.x * 128, As, Bs);
}

__global__ void combine_kernel(const float* __restrict__ h2o_w,
                               const float* __restrict__ l2h_w,
                               float* __restrict__ Md) {
    __shared__ float sW[16][17];
    __shared__ float sL[16][17];
    const int o = blockIdx.y * 16 + threadIdx.y;
    const int l = blockIdx.x * 16 + threadIdx.x;
    float acc = 0.0f;
    for (int h0 = 0; h0 < HID; h0 += 16) {
        sW[threadIdx.y][threadIdx.x] = h2o_w[(size_t)o * HID + h0 + threadIdx.x];
        sL[threadIdx.y][threadIdx.x] = l2h_w[(size_t)(h0 + threadIdx.y) * LAT + l];
        __syncthreads();
#pragma unroll
        for (int kk = 0; kk < 16; kk++) acc += sW[threadIdx.y][kk] * sL[kk][threadIdx.x];
        __syncthreads();
    }
    Md[(size_t)o * LAT + l] = acc;
}

__global__ void cvec_kernel(const float* __restrict__ h2o_w,
                            const float* __restrict__ l2h_b,
                            const float* __restrict__ h2o_b,
                            float* __restrict__ cd) {
    const int o = blockIdx.x * blockDim.x + threadIdx.x;
    if (o < OUTD) {
        float a = h2o_b[o];
        for (int h = 0; h < HID; h++) a += h2o_w[(size_t)o * HID + h] * l2h_b[h];
        cd[o] = a;
    }
}

// ---------------------------------------------------------------------------
// 4 graph nodes total: combine, cvec, persistent ODE, decoder GEMM.
// ---------------------------------------------------------------------------
extern "C" void kernel_launch(void* const* d_in, const int* in_sizes, int n_in,
                              void* d_out, int out_size) {
    const float* z0    = (const float*)d_in[0];
    const float* tv    = (const float*)d_in[1];
    const float* w1    = (const float*)d_in[2];
    const float* b1    = (const float*)d_in[3];
    const float* w2    = (const float*)d_in[4];
    const float* b2    = (const float*)d_in[5];
    const float* w3    = (const float*)d_in[6];
    const float* b3    = (const float*)d_in[7];
    const float* l2h_w = (const float*)d_in[8];
    const float* l2h_b = (const float*)d_in[9];
    const float* h2o_w = (const float*)d_in[10];
    const float* h2o_b = (const float*)d_in[11];
    float* out = (float*)d_out;

    float *zs, *h1, *h2, *za, *zb, *Md, *cd;
    cudaGetSymbolAddress((void**)&zs, g_zs);
    cudaGetSymbolAddress((void**)&h1, g_h1);
    cudaGetSymbolAddress((void**)&h2, g_h2);
    cudaGetSymbolAddress((void**)&za, g_za);
    cudaGetSymbolAddress((void**)&zb, g_zb);
    cudaGetSymbolAddress((void**)&Md, g_Md);
    cudaGetSymbolAddress((void**)&cd, g_cd);

    combine_kernel<<<dim3(LAT / 16, OUTD / 16), dim3(16, 16)>>>(h2o_w, l2h_w, Md);
    cvec_kernel<<<2, 256>>>(h2o_w, l2h_b, h2o_b, cd);

    ode_persistent<<<NCTA, 256>>>(z0, tv, w1, b1, w2, b2, w3, b3,
                                  zs, h1, h2, za, zb);

    decoder_gemm<<<dim3(OUTD / 128, TSTEPS * BATCH / 128), 256>>>(zs, Md, cd, out);
}

// round 4
// speedup vs baseline: 2.0962x; 2.0962x over previous
#include <cuda_runtime.h>
#include <math.h>
#include <cstdint>

// Problem constants
#define BATCH   2048
#define LAT     256
#define HID     1024
#define OUTD    512
#define TSTEPS  100
#define NSUB    10
#define NCTA    128

enum { MODE_ELU = 0, MODE_EULER = 1, MODE_PLAIN = 2 };

// ---------------------------------------------------------------------------
// Device scratch (no cudaMalloc allowed)
// ---------------------------------------------------------------------------
__device__ __align__(256) float g_zs[(size_t)TSTEPS * BATCH * LAT];
__device__ __align__(256) float g_h1[(size_t)BATCH * HID];
__device__ __align__(256) float g_h2[(size_t)BATCH * HID];
__device__ __align__(256) float g_za[(size_t)BATCH * LAT];
__device__ __align__(256) float g_zb[(size_t)BATCH * LAT];
__device__ __align__(256) float g_Md[(size_t)OUTD * LAT];
__device__ __align__(256) float g_cd[OUTD];

// grid-barrier state (returns to 0 each launch: even #barriers, count resets)
__device__ unsigned g_cnt;
__device__ unsigned g_sense;

// Dynamic smem: 4 tiles of 128 rows x 36 floats (stride-36 padding)
#define SA 36
#define TILE_FLOATS (128 * SA)
#define SMEM_BYTES (4 * TILE_FLOATS * 4)   // 73728 B

// ---------------------------------------------------------------------------
// Helpers
// ---------------------------------------------------------------------------
__device__ __forceinline__ float tf32_rna(float x) {
    uint32_t u;
    asm("cvt.rna.tf32.f32 %0, %1;" : "=r"(u) : "f"(x));
    return __uint_as_float(u);
}

// D += A*B  (m16n8k8, tf32 inputs as u32 bit patterns, fp32 accumulate)
__device__ __forceinline__ void mma8(float (&d)[4],
                                     uint32_t a0, uint32_t a1, uint32_t a2, uint32_t a3,
                                     uint32_t b0, uint32_t b1) {
    asm volatile(
        "mma.sync.aligned.m16n8k8.row.col.f32.tf32.tf32.f32 "
        "{%0,%1,%2,%3}, {%4,%5,%6,%7}, {%8,%9}, {%0,%1,%2,%3};"
        : "+f"(d[0]), "+f"(d[1]), "+f"(d[2]), "+f"(d[3])
        : "r"(a0), "r"(a1), "r"(a2), "r"(a3), "r"(b0), "r"(b1));
}

// ---------------------------------------------------------------------------
// Grid barrier: release/acquire at gpu scope (no MEMBAR.GPU, no L1D flush).
// ---------------------------------------------------------------------------
__device__ __forceinline__ void grid_sync(unsigned* s_sense) {
    __syncthreads();
    if (threadIdx.x == 0) {
        unsigned my = *s_sense ^ 1u;
        *s_sense = my;
        unsigned old;
        asm volatile("atom.release.gpu.global.add.u32 %0, [%1], %2;"
                     : "=r"(old) : "l"(&g_cnt), "r"(1u) : "memory");
        if (old == NCTA - 1u) {
            asm volatile("st.relaxed.gpu.global.u32 [%0], %1;" :: "l"(&g_cnt), "r"(0u) : "memory");
            asm volatile("st.release.gpu.global.u32 [%0], %1;" :: "l"(&g_sense), "r"(my) : "memory");
        } else {
            unsigned cur;
            do {
                asm volatile("ld.acquire.gpu.global.u32 %0, [%1];"
                             : "=r"(cur) : "l"(&g_sense) : "memory");
            } while (cur != my);
        }
    }
    __syncthreads();
}

// ---------------------------------------------------------------------------
// One BM x BN output tile:  C[m,n] = epilogue( sum_k A[m,k]*W[n,k] + bias[n] )
// 3-term tf32 split (AhBh + AhBl + AlBh), fp32 accumulators in registers.
// 256 threads = 8 warps in 4x2. BM,BN in {64,128}. K % 32 == 0.
// A (activations) read with __ldcg (cross-CTA producer); W/bias via __ldg.
// ---------------------------------------------------------------------------
template <int BM, int BN, int MODE>
__device__ __forceinline__ void tile_mma(
    const float* __restrict__ A, const float* __restrict__ W,
    const float* __restrict__ bias, const float* __restrict__ Zp,
    float* __restrict__ C, int N, int K, float h,
    int mB, int nB, float* sm) {

    constexpr int WM = BM / 4;        // warp tile M
    constexpr int WN = BN / 2;        // warp tile N
    constexpr int MT = WM / 16;       // mma tiles per warp (M)
    constexpr int NT = WN / 8;        // mma tiles per warp (N)
    constexpr int APT = BM * 8 / 256; // A float4 per thread per chunk
    constexpr int BPT = BN * 8 / 256; // B float4 per thread per chunk

    float* sAh = sm;
    float* sAl = sm + TILE_FLOATS;
    float* sBh = sm + 2 * TILE_FLOATS;
    float* sBl = sm + 3 * TILE_FLOATS;

    const int tid  = threadIdx.x;
    const int lane = tid & 31;
    const int warp = tid >> 5;
    const int wm   = warp >> 1;
    const int wn   = warp & 1;
    const int nTc  = K >> 5;

    float4 ra[APT], rb[BPT];
    float acc[MT][NT][4];
#pragma unroll
    for (int i = 0; i < MT; i++)
#pragma unroll
        for (int j = 0; j < NT; j++)
#pragma unroll
            for (int c = 0; c < 4; c++) acc[i][j][c] = 0.0f;

    auto ldg_chunk = [&](int t) {
#pragma unroll
        for (int i = 0; i < APT; i++) {
            int idx = tid + i * 256, row = idx >> 3, c4 = idx & 7;
            ra[i] = __ldcg((const float4*)(A + (size_t)(mB + row) * K + t * 32 + c4 * 4));
        }
#pragma unroll
        for (int i = 0; i < BPT; i++) {
            int idx = tid + i * 256, row = idx >> 3, c4 = idx & 7;
            rb[i] = __ldg((const float4*)(W + (size_t)(nB + row) * K + t * 32 + c4 * 4));
        }
    };
    auto sts_chunk = [&]() {
#pragma unroll
        for (int i = 0; i < APT; i++) {
            int idx = tid + i * 256, row = idx >> 3, c4 = idx & 7;
            float4 v = ra[i], hi, lo;
            hi.x = tf32_rna(v.x); lo.x = tf32_rna(v.x - hi.x);
            hi.y = tf32_rna(v.y); lo.y = tf32_rna(v.y - hi.y);
            hi.z = tf32_rna(v.z); lo.z = tf32_rna(v.z - hi.z);
            hi.w = tf32_rna(v.w); lo.w = tf32_rna(v.w - hi.w);
            *(float4*)(sAh + row * SA + c4 * 4) = hi;
            *(float4*)(sAl + row * SA + c4 * 4) = lo;
        }
#pragma unroll
        for (int i = 0; i < BPT; i++) {
            int idx = tid + i * 256, row = idx >> 3, c4 = idx & 7;
            float4 v = rb[i], hi, lo;
            hi.x = tf32_rna(v.x); lo.x = tf32_rna(v.x - hi.x);
            hi.y = tf32_rna(v.y); lo.y = tf32_rna(v.y - hi.y);
            hi.z = tf32_rna(v.z); lo.z = tf32_rna(v.z - hi.z);
            hi.w = tf32_rna(v.w); lo.w = tf32_rna(v.w - hi.w);
            *(float4*)(sBh + row * SA + c4 * 4) = hi;
            *(float4*)(sBl + row * SA + c4 * 4) = lo;
        }
    };

    ldg_chunk(0);
    sts_chunk();
    __syncthreads();

    const int rA = wm * WM + (lane >> 2);       // A fragment row base
    const int rB = wn * WN + (lane >> 2);       // B fragment n base
    const int cK = lane & 3;                    // fragment k base

    for (int t = 0; t < nTc; ++t) {
        if (t + 1 < nTc) ldg_chunk(t + 1);

#pragma unroll
        for (int k8 = 0; k8 < 4; k8++) {
            const int kb = k8 * 8 + cK;
            uint32_t ah[MT][4], al[MT][4], bh[NT][2], bl[NT][2];
#pragma unroll
            for (int i = 0; i < MT; i++) {
                const int r0 = (rA + i * 16) * SA, r1 = (rA + i * 16 + 8) * SA;
                ah[i][0] = __float_as_uint(sAh[r0 + kb]);
                ah[i][1] = __float_as_uint(sAh[r1 + kb]);
                ah[i][2] = __float_as_uint(sAh[r0 + kb + 4]);
                ah[i][3] = __float_as_uint(sAh[r1 + kb + 4]);
                al[i][0] = __float_as_uint(sAl[r0 + kb]);
                al[i][1] = __float_as_uint(sAl[r1 + kb]);
                al[i][2] = __float_as_uint(sAl[r0 + kb + 4]);
                al[i][3] = __float_as_uint(sAl[r1 + kb + 4]);
            }
#pragma unroll
            for (int j = 0; j < NT; j++) {
                const int rn = (rB + j * 8) * SA;
                bh[j][0] = __float_as_uint(sBh[rn + kb]);
                bh[j][1] = __float_as_uint(sBh[rn + kb + 4]);
                bl[j][0] = __float_as_uint(sBl[rn + kb]);
                bl[j][1] = __float_as_uint(sBl[rn + kb + 4]);
            }
#pragma unroll
            for (int i = 0; i < MT; i++)
#pragma unroll
                for (int j = 0; j < NT; j++) {
                    mma8(acc[i][j], ah[i][0], ah[i][1], ah[i][2], ah[i][3], bh[j][0], bh[j][1]);
                    mma8(acc[i][j], ah[i][0], ah[i][1], ah[i][2], ah[i][3], bl[j][0], bl[j][1]);
                    mma8(acc[i][j], al[i][0], al[i][1], al[i][2], al[i][3], bh[j][0], bh[j][1]);
                }
        }

        __syncthreads();
        if (t + 1 < nTc) {
            sts_chunk();
            __syncthreads();
        }
    }

    // ---- epilogue: bias + mode, float2 stores straight from accumulators ----
#pragma unroll
    for (int i = 0; i < MT; i++) {
        const int gm0 = mB + wm * WM + i * 16 + (lane >> 2);
#pragma unroll
        for (int j = 0; j < NT; j++) {
            const int gn = nB + wn * WN + j * 8 + (lane & 3) * 2;
            const float bi0 = __ldg(bias + gn), bi1 = __ldg(bias + gn + 1);
            float x0 = acc[i][j][0] + bi0, x1 = acc[i][j][1] + bi1;
            float x2 = acc[i][j][2] + bi0, x3 = acc[i][j][3] + bi1;
            if (MODE == MODE_ELU) {
                x0 = x0 > 0.0f ? x0 : expm1f(x0);
                x1 = x1 > 0.0f ? x1 : expm1f(x1);
                x2 = x2 > 0.0f ? x2 : expm1f(x2);
                x3 = x3 > 0.0f ? x3 : expm1f(x3);
            }
            const size_t g0 = (size_t)gm0 * N + gn;
            const size_t g1 = (size_t)(gm0 + 8) * N + gn;
            if (MODE == MODE_EULER) {
                float2 z0v = __ldcg((const float2*)(Zp + g0));
                float2 z1v = __ldcg((const float2*)(Zp + g1));
                x0 = z0v.x + h * x0; x1 = z0v.y + h * x1;
                x2 = z1v.x + h * x2; x3 = z1v.y + h * x3;
            }
            *(float2*)(C + g0) = make_float2(x0, x1);
            *(float2*)(C + g1) = make_float2(x2, x3);
        }
    }
}

// ---------------------------------------------------------------------------
// Persistent ODE integrator (grid = exactly NCTA x 256).
// Barriers per launch: 1 + 99*10*3 + 1 = 2972 (even -> g_sense ends at 0).
// ---------------------------------------------------------------------------
__global__ void __launch_bounds__(256, 1)
ode_persistent(const float* __restrict__ z0, const float* __restrict__ tv,
               const float* __restrict__ w1, const float* __restrict__ b1,
               const float* __restrict__ w2, const float* __restrict__ b2,
               const float* __restrict__ w3, const float* __restrict__ b3,
               float* __restrict__ zs, float* __restrict__ h1,
               float* __restrict__ h2, float* __restrict__ za,
               float* __restrict__ zb) {
    extern __shared__ float sm[];
    __shared__ unsigned s_sense;
    if (threadIdx.x == 0) s_sense = 0u;

    // zs[0] = z0
    for (int i = blockIdx.x * 256 + threadIdx.x; i < BATCH * LAT / 4; i += NCTA * 256)
        ((float4*)zs)[i] = __ldcg(((const float4*)z0) + i);
    grid_sync(&s_sense);                                    // barrier 1

    const int bx  = blockIdx.x;
    const int mB1 = (bx >> 3) * 128, nB1 = (bx & 7) * 128;  // 16x8 tiles of 128x128
    const int mB3 = (bx >> 2) * 64,  nB3 = (bx & 3) * 64;   // 32x4 tiles of 64x64
    const size_t BL = (size_t)BATCH * LAT;

    for (int it = 0; it < TSTEPS - 1; ++it) {
        const float hstep = (__ldg(tv + it + 1) - __ldg(tv + it)) * (1.0f / NSUB);
        for (int s = 0; s < NSUB; s++) {
            const float* zin  = (s == 0)        ? zs + (size_t)it * BL
                                                : ((s & 1) ? za : zb);
            float*       zout = (s == NSUB - 1) ? zs + (size_t)(it + 1) * BL
                                                : ((s & 1) ? zb : za);
            // h1 = elu(z @ w1.T + b1)   [2048x1024, K=256]
            tile_mma<128, 128, MODE_ELU>(zin, w1, b1, nullptr, h1,
                                         HID, LAT, 0.f, mB1, nB1, sm);
            grid_sync(&s_sense);
            // h2 = elu(h1 @ w2.T + b2)  [2048x1024, K=1024]
            tile_mma<128, 128, MODE_ELU>(h1, w2, b2, nullptr, h2,
                                         HID, HID, 0.f, mB1, nB1, sm);
            grid_sync(&s_sense);
            // zout = zin + h*(h2 @ w3.T + b3)  [2048x256, K=1024]
            tile_mma<64, 64, MODE_EULER>(h2, w3, b3, zin, zout,
                                         LAT, HID, hstep, mB3, nB3, sm);
            grid_sync(&s_sense);
        }
    }
    grid_sync(&s_sense);   // pad -> even count (2972)
}

// ---------------------------------------------------------------------------
// Folded decoder: out = zs @ Md.T + cd   (M=204800, N=512, K=256)
// ---------------------------------------------------------------------------
__global__ void __launch_bounds__(256, 1)
decoder_gemm(const float* __restrict__ zs, const float* __restrict__ Md,
             const float* __restrict__ cd, float* __restrict__ out) {
    extern __shared__ float sm[];
    tile_mma<128, 128, MODE_PLAIN>(zs, Md, cd, nullptr, out, OUTD, LAT, 0.f,
                                   blockIdx.y * 128, blockIdx.x * 128, sm);
}

// ---------------------------------------------------------------------------
// Decoder fold prep (tiny, once per launch)
// ---------------------------------------------------------------------------
__global__ void combine_kernel(const float* __restrict__ h2o_w,
                               const float* __restrict__ l2h_w,
                               float* __restrict__ Md) {
    __shared__ float sW[16][17];
    __shared__ float sL[16][17];
    const int o = blockIdx.y * 16 + threadIdx.y;
    const int l = blockIdx.x * 16 + threadIdx.x;
    float acc = 0.0f;
    for (int h0 = 0; h0 < HID; h0 += 16) {
        sW[threadIdx.y][threadIdx.x] = h2o_w[(size_t)o * HID + h0 + threadIdx.x];
        sL[threadIdx.y][threadIdx.x] = l2h_w[(size_t)(h0 + threadIdx.y) * LAT + l];
        __syncthreads();
#pragma unroll
        for (int kk = 0; kk < 16; kk++) acc += sW[threadIdx.y][kk] * sL[kk][threadIdx.x];
        __syncthreads();
    }
    Md[(size_t)o * LAT + l] = acc;
}

__global__ void cvec_kernel(const float* __restrict__ h2o_w,
                            const float* __restrict__ l2h_b,
                            const float* __restrict__ h2o_b,
                            float* __restrict__ cd) {
    const int o = blockIdx.x * blockDim.x + threadIdx.x;
    if (o < OUTD) {
        float a = h2o_b[o];
        for (int h = 0; h < HID; h++) a += h2o_w[(size_t)o * HID + h] * l2h_b[h];
        cd[o] = a;
    }
}

// ---------------------------------------------------------------------------
// 4 graph nodes: combine, cvec, persistent ODE, decoder.
// ---------------------------------------------------------------------------
extern "C" void kernel_launch(void* const* d_in, const int* in_sizes, int n_in,
                              void* d_out, int out_size) {
    const float* z0    = (const float*)d_in[0];
    const float* tv    = (const float*)d_in[1];
    const float* w1    = (const float*)d_in[2];
    const float* b1    = (const float*)d_in[3];
    const float* w2    = (const float*)d_in[4];
    const float* b2    = (const float*)d_in[5];
    const float* w3    = (const float*)d_in[6];
    const float* b3    = (const float*)d_in[7];
    const float* l2h_w = (const float*)d_in[8];
    const float* l2h_b = (const float*)d_in[9];
    const float* h2o_w = (const float*)d_in[10];
    const float* h2o_b = (const float*)d_in[11];
    float* out = (float*)d_out;

    float *zs, *h1, *h2, *za, *zb, *Md, *cd;
    cudaGetSymbolAddress((void**)&zs, g_zs);
    cudaGetSymbolAddress((void**)&h1, g_h1);
    cudaGetSymbolAddress((void**)&h2, g_h2);
    cudaGetSymbolAddress((void**)&za, g_za);
    cudaGetSymbolAddress((void**)&zb, g_zb);
    cudaGetSymbolAddress((void**)&Md, g_Md);
    cudaGetSymbolAddress((void**)&cd, g_cd);

    static bool attr_done = false;
    if (!attr_done) {
        cudaFuncSetAttribute(ode_persistent,
                             cudaFuncAttributeMaxDynamicSharedMemorySize, SMEM_BYTES);
        cudaFuncSetAttribute(decoder_gemm,
                             cudaFuncAttributeMaxDynamicSharedMemorySize, SMEM_BYTES);
        attr_done = true;
    }

    combine_kernel<<<dim3(LAT / 16, OUTD / 16), dim3(16, 16)>>>(h2o_w, l2h_w, Md);
    cvec_kernel<<<2, 256>>>(h2o_w, l2h_b, h2o_b, cd);

    ode_persistent<<<NCTA, 256, SMEM_BYTES>>>(z0, tv, w1, b1, w2, b2, w3, b3,
                                              zs, h1, h2, za, zb);

    decoder_gemm<<<dim3(OUTD / 128, TSTEPS * BATCH / 128), 256, SMEM_BYTES>>>(zs, Md, cd, out);
}